// round 5
// baseline (speedup 1.0000x reference)
#include <cuda_runtime.h>
#include <cuda_bf16.h>
#include <cstdint>
#include <math.h>

// Problem shapes (fixed)
#define NX 4096
#define NY 16384
#define CX 128
#define CY 128
#define OD 256
#define KIN 256
#define BIGD 1e30f
#define W_EPS 1e-16f
#define LN_EPS 1e-5f

// Global scratch: pre-split A (concat(interp|y)) and W, bf16 hi/lo
__device__ __nv_bfloat16 g_Ah[NY * KIN];
__device__ __nv_bfloat16 g_Al[NY * KIN];
__device__ __nv_bfloat16 g_Wh[OD * KIN];
__device__ __nv_bfloat16 g_Wl[OD * KIN];

// ---------------------------------------------------------------------------
// Helpers (baseline PTX, valid for compute_100)
// ---------------------------------------------------------------------------
static __device__ __forceinline__ uint32_t smem_u32(const void* p) {
    uint32_t a;
    asm("{ .reg .u64 t; cvta.to.shared.u64 t, %1; cvt.u32.u64 %0, t; }"
        : "=r"(a) : "l"(p));
    return a;
}

static __device__ __forceinline__ void ldsm_x4(uint32_t addr, uint32_t& r0, uint32_t& r1,
                                               uint32_t& r2, uint32_t& r3) {
    asm volatile("ldmatrix.sync.aligned.m8n8.x4.shared.b16 {%0,%1,%2,%3}, [%4];"
                 : "=r"(r0), "=r"(r1), "=r"(r2), "=r"(r3) : "r"(addr));
}

static __device__ __forceinline__ void mma_bf16(float* d, const uint32_t* a,
                                                uint32_t b0, uint32_t b1) {
    asm volatile(
        "mma.sync.aligned.m16n8k16.row.col.f32.bf16.bf16.f32 "
        "{%0,%1,%2,%3},{%4,%5,%6,%7},{%8,%9},{%0,%1,%2,%3};"
        : "+f"(d[0]), "+f"(d[1]), "+f"(d[2]), "+f"(d[3])
        : "r"(a[0]), "r"(a[1]), "r"(a[2]), "r"(a[3]), "r"(b0), "r"(b1));
}

static __device__ __forceinline__ void cp_async16(uint32_t dst, const void* src) {
    asm volatile("cp.async.cg.shared.global [%0], [%1], 16;" :: "r"(dst), "l"(src));
}
static __device__ __forceinline__ void cp_commit() {
    asm volatile("cp.async.commit_group;" ::: "memory");
}
template <int N>
static __device__ __forceinline__ void cp_wait() {
    asm volatile("cp.async.wait_group %0;" :: "n"(N) : "memory");
}

static __device__ __forceinline__ uint32_t pack_hi(float v0, float v1) {
    __nv_bfloat16 h0 = __float2bfloat16_rn(v0);
    __nv_bfloat16 h1 = __float2bfloat16_rn(v1);
    return (uint32_t)__bfloat16_as_ushort(h0) | ((uint32_t)__bfloat16_as_ushort(h1) << 16);
}
static __device__ __forceinline__ uint32_t pack_lo(float v0, float v1) {
    __nv_bfloat16 h0 = __float2bfloat16_rn(v0);
    __nv_bfloat16 h1 = __float2bfloat16_rn(v1);
    __nv_bfloat16 l0 = __float2bfloat16_rn(v0 - __bfloat162float(h0));
    __nv_bfloat16 l1 = __float2bfloat16_rn(v1 - __bfloat162float(h1));
    return (uint32_t)__bfloat16_as_ushort(l0) | ((uint32_t)__bfloat16_as_ushort(l1) << 16);
}

// ---------------------------------------------------------------------------
// Kernel 1: KNN + interpolation + A/W bf16 hi-lo pre-split
//   blocks [0, 2048):    8 warps = 8 queries; block-shared batch boundaries
//   blocks [2048, 2080): W split (packed u32 stores)
// ---------------------------------------------------------------------------
#define KNN_BLOCKS 2048
#define W_BLOCKS 32

__global__ void prep_kernel(const float* __restrict__ pos_x,
                            const float* __restrict__ xfeat,
                            const int*   __restrict__ batch_x,
                            const float* __restrict__ pos_y,
                            const float* __restrict__ yfeat,
                            const int*   __restrict__ batch_y,
                            const float* __restrict__ W)
{
    if (blockIdx.x >= KNN_BLOCKS) {
        // W split: 8192 threads x 4 pairs = 32768 pairs (= OD*KIN/2)
        int base = ((int)blockIdx.x - KNN_BLOCKS) * (256 * 4) + threadIdx.x;
        uint32_t* wh = (uint32_t*)g_Wh;
        uint32_t* wl = (uint32_t*)g_Wl;
#pragma unroll
        for (int i = 0; i < 4; i++) {
            int p = base + i * 256;             // pair index
            float2 v = *(const float2*)&W[p * 2];
            wh[p] = pack_hi(v.x, v.y);
            wl[p] = pack_lo(v.x, v.y);
        }
        return;
    }

    // ---- per-block batch boundaries (batch_x sorted) ----
    __shared__ int bounds[9];
    if (threadIdx.x < 9) {
        int t = threadIdx.x;
        int lo = 0, hi = NX;
        while (lo < hi) { int m = (lo + hi) >> 1; if (batch_x[m] < t) lo = m + 1; else hi = m; }
        bounds[t] = lo;
    }
    __syncthreads();

    int gwarp = (blockIdx.x * blockDim.x + threadIdx.x) >> 5;
    int lane  = threadIdx.x & 31;
    const int yi = gwarp;

    const float py0 = pos_y[yi * 3 + 0];
    const float py1 = pos_y[yi * 3 + 1];
    const float py2 = pos_y[yi * 3 + 2];
    const float ny2 = py0 * py0 + py1 * py1 + py2 * py2;
    const int b = batch_y[yi];
    const int s = bounds[b];
    const int e = bounds[b + 1];

    float d0 = BIGD, d1 = BIGD, d2v = BIGD;
    int   i0 = 0,    i1 = 0,    i2 = 0;

#define INSERT(dd, jj)                                                          \
    do {                                                                        \
        float _d = (dd); int _j = (jj);                                         \
        if (_d < d0 || (_d == d0 && _j < i0)) {                                 \
            d2v = d1; i2 = i1; d1 = d0; i1 = i0; d0 = _d; i0 = _j;              \
        } else if (_d < d1 || (_d == d1 && _j < i1)) {                          \
            d2v = d1; i2 = i1; d1 = _d; i1 = _j;                                \
        } else if (_d < d2v || (_d == d2v && _j < i2)) {                        \
            d2v = _d; i2 = _j;                                                  \
        }                                                                       \
    } while (0)

    for (int j = s + lane; j < e; j += 32) {
        float px0 = pos_x[j * 3 + 0];
        float px1 = pos_x[j * 3 + 1];
        float px2 = pos_x[j * 3 + 2];
        float nx2 = px0 * px0 + px1 * px1 + px2 * px2;
        float dot = py0 * px0 + py1 * px1 + py2 * px2;
        float d = fmaxf(ny2 + nx2 - 2.0f * dot, 0.0f);
        INSERT(d, j);
    }
    for (int off = 16; off; off >>= 1) {
        float od0 = __shfl_xor_sync(0xffffffffu, d0,  off);
        float od1 = __shfl_xor_sync(0xffffffffu, d1,  off);
        float od2 = __shfl_xor_sync(0xffffffffu, d2v, off);
        int   oi0 = __shfl_xor_sync(0xffffffffu, i0,  off);
        int   oi1 = __shfl_xor_sync(0xffffffffu, i1,  off);
        int   oi2 = __shfl_xor_sync(0xffffffffu, i2,  off);
        INSERT(od0, oi0);
        INSERT(od1, oi1);
        INSERT(od2, oi2);
    }
#undef INSERT

    const float w0 = 1.0f / fmaxf(d0,  W_EPS);
    const float w1 = 1.0f / fmaxf(d1,  W_EPS);
    const float w2 = 1.0f / fmaxf(d2v, W_EPS);
    const float inv_wsum = 1.0f / (w0 + w1 + w2);

    const float* f0 = xfeat + (size_t)i0 * CX;
    const float* f1 = xfeat + (size_t)i1 * CX;
    const float* f2 = xfeat + (size_t)i2 * CX;
    const float* fy = yfeat + (size_t)yi * CY;
    uint32_t* ah = (uint32_t*)(g_Ah + (size_t)yi * KIN);
    uint32_t* al = (uint32_t*)(g_Al + (size_t)yi * KIN);

#pragma unroll
    for (int it = 0; it < 2; it++) {
        int cp = lane + it * 32;               // col-pair 0..63
        int c  = cp * 2;
        float2 a0 = *(const float2*)&f0[c];
        float2 a1 = *(const float2*)&f1[c];
        float2 a2 = *(const float2*)&f2[c];
        float2 ay = *(const float2*)&fy[c];
        float v0 = (w0 * a0.x + w1 * a1.x + w2 * a2.x) * inv_wsum;
        float v1 = (w0 * a0.y + w1 * a1.y + w2 * a2.y) * inv_wsum;
        ah[cp] = pack_hi(v0, v1);
        al[cp] = pack_lo(v0, v1);
        ah[CX / 2 + cp] = pack_hi(ay.x, ay.y);
        al[CX / 2 + cp] = pack_lo(ay.x, ay.y);
    }
}

// ---------------------------------------------------------------------------
// Kernel 2: bf16 hi/lo-split mma.sync GEMM + LN + ReLU
// Per CTA: 128 rows x 256 cols, K=256. 512 threads = 16 warps = 4(m) x 4(n);
// warp tile 32(m) x 16(n) per 64-col chunk. N in 4 chunks x 2 kinds (Wh/Wl),
// double-buffered via cp.async.
// SMEM: A_hi/A_lo [128][264bf16] @ 0/67584, B x2 [64][264bf16] @ 135168
// ---------------------------------------------------------------------------
#define SROW 528
#define A_HI 0
#define A_LO 67584
#define B_BASE 135168
#define B_BUF 33792
#define SM_TOTAL 202752

__global__ __launch_bounds__(512, 1)
void gemm_mma_kernel(const float* __restrict__ gamma,
                     const float* __restrict__ beta,
                     float* __restrict__ out)
{
    extern __shared__ char smem[];
    const uint32_t sb = smem_u32(smem);

    const int tid  = threadIdx.x;
    const int wid  = tid >> 5;
    const int lane = tid & 31;
    const int g    = lane >> 2;
    const int tig  = lane & 3;
    const int mw   = (wid >> 2) * 32;      // warp row base (0..96)
    const int nw   = wid & 3;              // warp 16-col group within chunk
    const int rowBase = blockIdx.x * 128;

    // ---- prologue: cp.async A (hi+lo) + B phase 0 (Wh chunk 0) ----
#pragma unroll
    for (int i = 0; i < 8; i++) {
        int idx = tid + i * 512;               // 0..4095
        int r = idx >> 5, kc = idx & 31;
        const size_t gs = (size_t)(rowBase + r) * KIN + kc * 8;
        uint32_t off = (uint32_t)(r * SROW + kc * 16);
        cp_async16(sb + A_HI + off, &g_Ah[gs]);
        cp_async16(sb + A_LO + off, &g_Al[gs]);
    }
#pragma unroll
    for (int i = 0; i < 4; i++) {
        int idx = tid + i * 512;               // 0..2047
        int r = idx >> 5, kc = idx & 31;
        cp_async16(sb + B_BASE + (uint32_t)(r * SROW + kc * 16),
                   &g_Wh[(size_t)r * KIN + kc * 8]);
    }
    cp_commit();

    // ---- per-lane ldmatrix offsets ----
    const int quad  = lane >> 3;
    const int lrow  = lane & 7;
    const int aRow  = (quad & 1) * 8 + lrow;
    const int aKoff = (quad >> 1) * 8;
    const uint32_t offA0 = (uint32_t)((mw + aRow) * SROW + aKoff * 2);
    const uint32_t offA1 = (uint32_t)((mw + 16 + aRow) * SROW + aKoff * 2);
    const int bRow  = nw * 16 + ((lane >> 4) * 8) + lrow;
    const int bKoff = ((lane >> 3) & 1) * 8;
    const uint32_t offB = (uint32_t)(bRow * SROW + bKoff * 2);

    float acc[4][2][2][4];
#pragma unroll
    for (int c = 0; c < 4; c++)
#pragma unroll
        for (int mt = 0; mt < 2; mt++)
#pragma unroll
            for (int nt = 0; nt < 2; nt++)
#pragma unroll
                for (int j = 0; j < 4; j++) acc[c][mt][nt][j] = 0.f;

    // ---- main loop: 8 phases (chunk = p>>1, kind = p&1: 0=Wh, 1=Wl) ----
#pragma unroll
    for (int p = 0; p < 8; p++) {
        const int c = p >> 1;
        const int kind = p & 1;
        __syncthreads();
        if (p < 7) {
            const int pn = p + 1;
            const int cn = pn >> 1;
            const __nv_bfloat16* src = (pn & 1) ? g_Wl : g_Wh;
            uint32_t dstb = sb + B_BASE + (uint32_t)(pn & 1) * B_BUF;
#pragma unroll
            for (int i = 0; i < 4; i++) {
                int idx = tid + i * 512;
                int r = idx >> 5, kc = idx & 31;
                cp_async16(dstb + (uint32_t)(r * SROW + kc * 16),
                           &src[(size_t)(cn * 64 + r) * KIN + kc * 8]);
            }
            cp_commit();
            cp_wait<1>();
        } else {
            cp_wait<0>();
        }
        __syncthreads();

        const uint32_t ba  = sb + B_BASE + (uint32_t)(p & 1) * B_BUF + offB;
        const uint32_t ah0 = sb + A_HI + offA0;
        const uint32_t ah1 = sb + A_HI + offA1;
        const uint32_t al0 = sb + A_LO + offA0;
        const uint32_t al1 = sb + A_LO + offA1;

        if (kind == 0) {
#pragma unroll 8
            for (int ks = 0; ks < 16; ks++) {
                const uint32_t kb = (uint32_t)(ks * 32);
                uint32_t Ah0[4], Ah1[4], Al0[4], Al1[4], Bf[4];
                ldsm_x4(ba + kb, Bf[0], Bf[1], Bf[2], Bf[3]);
                ldsm_x4(ah0 + kb, Ah0[0], Ah0[1], Ah0[2], Ah0[3]);
                ldsm_x4(ah1 + kb, Ah1[0], Ah1[1], Ah1[2], Ah1[3]);
                ldsm_x4(al0 + kb, Al0[0], Al0[1], Al0[2], Al0[3]);
                ldsm_x4(al1 + kb, Al1[0], Al1[1], Al1[2], Al1[3]);
#pragma unroll
                for (int nt = 0; nt < 2; nt++) {
                    uint32_t b0 = Bf[2 * nt], b1 = Bf[2 * nt + 1];
                    mma_bf16(acc[c][0][nt], Ah0, b0, b1);
                    mma_bf16(acc[c][1][nt], Ah1, b0, b1);
                    mma_bf16(acc[c][0][nt], Al0, b0, b1);
                    mma_bf16(acc[c][1][nt], Al1, b0, b1);
                }
            }
        } else {
#pragma unroll 8
            for (int ks = 0; ks < 16; ks++) {
                const uint32_t kb = (uint32_t)(ks * 32);
                uint32_t Ah0[4], Ah1[4], Bf[4];
                ldsm_x4(ba + kb, Bf[0], Bf[1], Bf[2], Bf[3]);
                ldsm_x4(ah0 + kb, Ah0[0], Ah0[1], Ah0[2], Ah0[3]);
                ldsm_x4(ah1 + kb, Ah1[0], Ah1[1], Ah1[2], Ah1[3]);
#pragma unroll
                for (int nt = 0; nt < 2; nt++) {
                    uint32_t b0 = Bf[2 * nt], b1 = Bf[2 * nt + 1];
                    mma_bf16(acc[c][0][nt], Ah0, b0, b1);
                    mma_bf16(acc[c][1][nt], Ah1, b0, b1);
                }
            }
        }
    }
    __syncthreads();

    // ---- LayerNorm stats (reuse B smem region) ----
    float* sSum = (float*)(smem + B_BASE);    // [128][4]
    float* sSq  = sSum + 512;                 // [128][4]
    float* sMu  = sSq + 512;                  // [128]
    float* sRs  = sMu + 128;                  // [128]

#pragma unroll
    for (int mt = 0; mt < 2; mt++)
#pragma unroll
        for (int half = 0; half < 2; half++) {
            float s = 0.f, q = 0.f;
#pragma unroll
            for (int c = 0; c < 4; c++)
#pragma unroll
                for (int nt = 0; nt < 2; nt++)
#pragma unroll
                    for (int j = 0; j < 2; j++) {
                        float v = acc[c][mt][nt][half * 2 + j];
                        s += v; q += v * v;
                    }
            s += __shfl_xor_sync(0xffffffffu, s, 1);
            q += __shfl_xor_sync(0xffffffffu, q, 1);
            s += __shfl_xor_sync(0xffffffffu, s, 2);
            q += __shfl_xor_sync(0xffffffffu, q, 2);
            if (tig == 0) {
                int row = mw + mt * 16 + half * 8 + g;
                sSum[row * 4 + nw] = s;
                sSq[row * 4 + nw]  = q;
            }
        }
    __syncthreads();

    if (tid < 128) {
        float s = sSum[tid * 4] + sSum[tid * 4 + 1] + sSum[tid * 4 + 2] + sSum[tid * 4 + 3];
        float q = sSq[tid * 4] + sSq[tid * 4 + 1] + sSq[tid * 4 + 2] + sSq[tid * 4 + 3];
        float mu = s * (1.0f / OD);
        float var = fmaxf(q * (1.0f / OD) - mu * mu, 0.0f);
        sMu[tid] = mu;
        sRs[tid] = rsqrtf(var + LN_EPS);
    }
    __syncthreads();

    // ---- normalize + affine + ReLU + store ----
#pragma unroll
    for (int mt = 0; mt < 2; mt++)
#pragma unroll
        for (int half = 0; half < 2; half++) {
            int row = mw + mt * 16 + half * 8 + g;
            float mu = sMu[row];
            float rs = sRs[row];
            float* orow = out + (size_t)(rowBase + row) * OD;
#pragma unroll
            for (int c = 0; c < 4; c++)
#pragma unroll
                for (int nt = 0; nt < 2; nt++) {
                    int col = c * 64 + nw * 16 + nt * 8 + tig * 2;
                    float2 gb0 = *(const float2*)&gamma[col];
                    float2 bb0 = *(const float2*)&beta[col];
                    float v0 = acc[c][mt][nt][half * 2 + 0];
                    float v1 = acc[c][mt][nt][half * 2 + 1];
                    float2 r2;
                    r2.x = fmaxf((v0 - mu) * rs * gb0.x + bb0.x, 0.0f);
                    r2.y = fmaxf((v1 - mu) * rs * gb0.y + bb0.y, 0.0f);
                    *(float2*)&orow[col] = r2;
                }
        }
}

// ---------------------------------------------------------------------------
extern "C" void kernel_launch(void* const* d_in, const int* in_sizes, int n_in,
                              void* d_out, int out_size)
{
    const float* pos_x   = (const float*)d_in[0];
    const float* xfeat   = (const float*)d_in[1];
    const int*   batch_x = (const int*)  d_in[2];
    const float* pos_y   = (const float*)d_in[3];
    const float* yfeat   = (const float*)d_in[4];
    const int*   batch_y = (const int*)  d_in[5];
    const float* W       = (const float*)d_in[6];
    const float* gamma   = (const float*)d_in[7];
    const float* beta    = (const float*)d_in[8];
    float* out = (float*)d_out;

    prep_kernel<<<KNN_BLOCKS + W_BLOCKS, 256>>>(pos_x, xfeat, batch_x,
                                                pos_y, yfeat, batch_y, W);

    cudaFuncSetAttribute(gemm_mma_kernel,
                         cudaFuncAttributeMaxDynamicSharedMemorySize, SM_TOTAL);
    gemm_mma_kernel<<<NY / 128, 512, SM_TOTAL>>>(gamma, beta, out);
}

// round 6
// speedup vs baseline: 1.0551x; 1.0551x over previous
#include <cuda_runtime.h>
#include <cuda_bf16.h>
#include <cstdint>
#include <math.h>

// Problem shapes (fixed)
#define NX 4096
#define NY 16384
#define CX 128
#define CY 128
#define OD 256
#define KIN 256
#define BIGD 1e30f
#define W_EPS 1e-16f
#define LN_EPS 1e-5f

// Global scratch: pre-split A (concat(interp|y)) and W, bf16 hi/lo
__device__ __nv_bfloat16 g_Ah[NY * KIN];
__device__ __nv_bfloat16 g_Al[NY * KIN];
__device__ __nv_bfloat16 g_Wh[OD * KIN];
__device__ __nv_bfloat16 g_Wl[OD * KIN];

// ---------------------------------------------------------------------------
// Helpers (baseline PTX, valid for compute_100)
// ---------------------------------------------------------------------------
static __device__ __forceinline__ uint32_t smem_u32(const void* p) {
    uint32_t a;
    asm("{ .reg .u64 t; cvta.to.shared.u64 t, %1; cvt.u32.u64 %0, t; }"
        : "=r"(a) : "l"(p));
    return a;
}

static __device__ __forceinline__ void ldsm_x4(uint32_t addr, uint32_t& r0, uint32_t& r1,
                                               uint32_t& r2, uint32_t& r3) {
    asm volatile("ldmatrix.sync.aligned.m8n8.x4.shared.b16 {%0,%1,%2,%3}, [%4];"
                 : "=r"(r0), "=r"(r1), "=r"(r2), "=r"(r3) : "r"(addr));
}

static __device__ __forceinline__ void mma_bf16(float* d, const uint32_t* a,
                                                uint32_t b0, uint32_t b1) {
    asm volatile(
        "mma.sync.aligned.m16n8k16.row.col.f32.bf16.bf16.f32 "
        "{%0,%1,%2,%3},{%4,%5,%6,%7},{%8,%9},{%0,%1,%2,%3};"
        : "+f"(d[0]), "+f"(d[1]), "+f"(d[2]), "+f"(d[3])
        : "r"(a[0]), "r"(a[1]), "r"(a[2]), "r"(a[3]), "r"(b0), "r"(b1));
}

static __device__ __forceinline__ void cp_async16(uint32_t dst, const void* src) {
    asm volatile("cp.async.cg.shared.global [%0], [%1], 16;" :: "r"(dst), "l"(src));
}
static __device__ __forceinline__ void cp_commit() {
    asm volatile("cp.async.commit_group;" ::: "memory");
}
template <int N>
static __device__ __forceinline__ void cp_wait() {
    asm volatile("cp.async.wait_group %0;" :: "n"(N) : "memory");
}

static __device__ __forceinline__ uint32_t pack_hi(float v0, float v1) {
    __nv_bfloat16 h0 = __float2bfloat16_rn(v0);
    __nv_bfloat16 h1 = __float2bfloat16_rn(v1);
    return (uint32_t)__bfloat16_as_ushort(h0) | ((uint32_t)__bfloat16_as_ushort(h1) << 16);
}
static __device__ __forceinline__ uint32_t pack_lo(float v0, float v1) {
    __nv_bfloat16 h0 = __float2bfloat16_rn(v0);
    __nv_bfloat16 h1 = __float2bfloat16_rn(v1);
    __nv_bfloat16 l0 = __float2bfloat16_rn(v0 - __bfloat162float(h0));
    __nv_bfloat16 l1 = __float2bfloat16_rn(v1 - __bfloat162float(h1));
    return (uint32_t)__bfloat16_as_ushort(l0) | ((uint32_t)__bfloat16_as_ushort(l1) << 16);
}

// Branchless lexicographic top-3 insert (pure select, no BSSY/BSYNC)
#define BINSERT(dd, jj)                                                         \
    do {                                                                        \
        float _d = (dd); int _j = (jj);                                         \
        bool lt0 = (_d < d0) || (_d == d0 && _j < i0);                          \
        bool lt1 = (_d < d1) || (_d == d1 && _j < i1);                          \
        bool lt2 = (_d < d2v) || (_d == d2v && _j < i2);                        \
        d2v = lt1 ? d1 : (lt2 ? _d : d2v); i2 = lt1 ? i1 : (lt2 ? _j : i2);     \
        d1  = lt0 ? d0 : (lt1 ? _d : d1);  i1 = lt0 ? i0 : (lt1 ? _j : i1);     \
        d0  = lt0 ? _d : d0;               i0 = lt0 ? _j : i0;                  \
    } while (0)

// ---------------------------------------------------------------------------
// Kernel 1: KNN + interpolation + A/W bf16 hi-lo pre-split
//   blocks [0, 2048):    8 warps = 8 queries; block-shared pos_x segment cache
//   blocks [2048, 2080): W split (packed u32 stores)
// ---------------------------------------------------------------------------
#define KNN_BLOCKS 2048
#define W_BLOCKS 32
#define MAXP 2048

__global__ void prep_kernel(const float* __restrict__ pos_x,
                            const float* __restrict__ xfeat,
                            const int*   __restrict__ batch_x,
                            const float* __restrict__ pos_y,
                            const float* __restrict__ yfeat,
                            const int*   __restrict__ batch_y,
                            const float* __restrict__ W)
{
    if (blockIdx.x >= KNN_BLOCKS) {
        int base = ((int)blockIdx.x - KNN_BLOCKS) * (256 * 4) + threadIdx.x;
        uint32_t* wh = (uint32_t*)g_Wh;
        uint32_t* wl = (uint32_t*)g_Wl;
#pragma unroll
        for (int i = 0; i < 4; i++) {
            int p = base + i * 256;
            float2 v = *(const float2*)&W[p * 2];
            wh[p] = pack_hi(v.x, v.y);
            wl[p] = pack_lo(v.x, v.y);
        }
        return;
    }

    __shared__ float spx[MAXP], spy[MAXP], spz[MAXP], snrm[MAXP];
    __shared__ int sbounds[9];

    const int tid = threadIdx.x;
    if (tid < 9) {
        int t = tid;
        int lo = 0, hi = NX;
        while (lo < hi) { int m = (lo + hi) >> 1; if (batch_x[m] < t) lo = m + 1; else hi = m; }
        sbounds[t] = lo;
    }
    __syncthreads();

    const int q0   = blockIdx.x * 8;
    const int bmin = batch_y[q0];
    const int bmax = batch_y[q0 + 7];
    const int s0   = sbounds[bmin];
    const int e1   = sbounds[bmax + 1];
    const int n    = e1 - s0;
    const bool useSmem = (n <= MAXP);

    if (useSmem) {
        for (int i = tid; i < n; i += 256) {
            int j = s0 + i;
            float x = pos_x[j * 3 + 0];
            float y = pos_x[j * 3 + 1];
            float z = pos_x[j * 3 + 2];
            spx[i] = x; spy[i] = y; spz[i] = z;
            snrm[i] = x * x + y * y + z * z;
        }
    }
    __syncthreads();

    const int lane = tid & 31;
    const int yi   = q0 + (tid >> 5);

    const float py0 = pos_y[yi * 3 + 0];
    const float py1 = pos_y[yi * 3 + 1];
    const float py2 = pos_y[yi * 3 + 2];
    const float ny2 = py0 * py0 + py1 * py1 + py2 * py2;
    const int b = batch_y[yi];
    const int s = sbounds[b];
    const int e = sbounds[b + 1];

    float d0 = BIGD, d1 = BIGD, d2v = BIGD;
    int   i0 = 0,    i1 = 0,    i2 = 0;

    if (useSmem) {
        const int ls = s - s0, le = e - s0;
        for (int jl = ls + lane; jl < le; jl += 32) {
            float dot = py0 * spx[jl] + py1 * spy[jl] + py2 * spz[jl];
            float d = fmaxf(ny2 + snrm[jl] - 2.0f * dot, 0.0f);
            BINSERT(d, s0 + jl);
        }
    } else {
        for (int j = s + lane; j < e; j += 32) {
            float px0 = pos_x[j * 3 + 0];
            float px1 = pos_x[j * 3 + 1];
            float px2 = pos_x[j * 3 + 2];
            float nx2 = px0 * px0 + px1 * px1 + px2 * px2;
            float dot = py0 * px0 + py1 * px1 + py2 * px2;
            float d = fmaxf(ny2 + nx2 - 2.0f * dot, 0.0f);
            BINSERT(d, j);
        }
    }

    for (int off = 16; off; off >>= 1) {
        float od0 = __shfl_xor_sync(0xffffffffu, d0,  off);
        float od1 = __shfl_xor_sync(0xffffffffu, d1,  off);
        float od2 = __shfl_xor_sync(0xffffffffu, d2v, off);
        int   oi0 = __shfl_xor_sync(0xffffffffu, i0,  off);
        int   oi1 = __shfl_xor_sync(0xffffffffu, i1,  off);
        int   oi2 = __shfl_xor_sync(0xffffffffu, i2,  off);
        BINSERT(od0, oi0);
        BINSERT(od1, oi1);
        BINSERT(od2, oi2);
    }

    const float w0 = 1.0f / fmaxf(d0,  W_EPS);
    const float w1 = 1.0f / fmaxf(d1,  W_EPS);
    const float w2 = 1.0f / fmaxf(d2v, W_EPS);
    const float inv_wsum = 1.0f / (w0 + w1 + w2);

    const float* f0 = xfeat + (size_t)i0 * CX;
    const float* f1 = xfeat + (size_t)i1 * CX;
    const float* f2 = xfeat + (size_t)i2 * CX;
    const float* fy = yfeat + (size_t)yi * CY;
    uint2* ah = (uint2*)(g_Ah + (size_t)yi * KIN);
    uint2* al = (uint2*)(g_Al + (size_t)yi * KIN);

    {
        int c = lane * 4;                      // cols c..c+3 of interp half
        float4 a0 = *(const float4*)&f0[c];
        float4 a1 = *(const float4*)&f1[c];
        float4 a2 = *(const float4*)&f2[c];
        float4 ay = *(const float4*)&fy[c];
        float v0 = (w0 * a0.x + w1 * a1.x + w2 * a2.x) * inv_wsum;
        float v1 = (w0 * a0.y + w1 * a1.y + w2 * a2.y) * inv_wsum;
        float v2 = (w0 * a0.z + w1 * a1.z + w2 * a2.z) * inv_wsum;
        float v3 = (w0 * a0.w + w1 * a1.w + w2 * a2.w) * inv_wsum;
        ah[lane]      = make_uint2(pack_hi(v0, v1), pack_hi(v2, v3));
        al[lane]      = make_uint2(pack_lo(v0, v1), pack_lo(v2, v3));
        ah[32 + lane] = make_uint2(pack_hi(ay.x, ay.y), pack_hi(ay.z, ay.w));
        al[32 + lane] = make_uint2(pack_lo(ay.x, ay.y), pack_lo(ay.z, ay.w));
    }
}

// ---------------------------------------------------------------------------
// Kernel 2: bf16 hi/lo-split mma.sync GEMM + LN + ReLU
// Per CTA: 64 rows x 256 cols, K=256. 128 threads = 4 warps = 2(m) x 2(n),
// warp tile 32x32 (best MMA/LDSM ratio). N in 4 chunks x 2 kinds (Wh/Wl) =
// 8 phases, single B buffer; 2 CTAs/SM provide cross-CTA overlap.
// SMEM: A_hi [64][264bf16] @0, A_lo @33792, B [64][264bf16] @67584. 99 KB.
// ---------------------------------------------------------------------------
#define SROW 528
#define GA_HI 0
#define GA_LO 33792
#define GB 67584
#define G_TOTAL 101376

__global__ __launch_bounds__(128, 2)
void gemm_mma_kernel(const float* __restrict__ gamma,
                     const float* __restrict__ beta,
                     float* __restrict__ out)
{
    extern __shared__ char smem[];
    const uint32_t sb = smem_u32(smem);

    const int tid  = threadIdx.x;
    const int wid  = tid >> 5;
    const int lane = tid & 31;
    const int g    = lane >> 2;
    const int tig  = lane & 3;
    const int mw   = (wid >> 1) * 32;      // warp row base (0/32)
    const int wn   = wid & 1;              // warp n-half within 64-col chunk
    const int rowBase = blockIdx.x * 64;

    // ---- prologue: cp.async A (hi+lo) + B phase 0 (Wh chunk 0) ----
#pragma unroll
    for (int i = 0; i < 16; i++) {
        int idx = tid + i * 128;               // 0..2047
        int r = idx >> 5, kc = idx & 31;
        const size_t gs = (size_t)(rowBase + r) * KIN + kc * 8;
        uint32_t off = (uint32_t)(r * SROW + kc * 16);
        cp_async16(sb + GA_HI + off, &g_Ah[gs]);
        cp_async16(sb + GA_LO + off, &g_Al[gs]);
    }
#pragma unroll
    for (int i = 0; i < 16; i++) {
        int idx = tid + i * 128;               // 0..2047
        int r = idx >> 5, kc = idx & 31;
        cp_async16(sb + GB + (uint32_t)(r * SROW + kc * 16),
                   &g_Wh[(size_t)r * KIN + kc * 8]);
    }
    cp_commit();

    // ---- per-lane ldmatrix offsets ----
    const int quad  = lane >> 3;
    const int lrow  = lane & 7;
    const int aRow  = (quad & 1) * 8 + lrow;
    const int aKoff = (quad >> 1) * 8;
    const uint32_t offA0 = (uint32_t)((mw + aRow) * SROW + aKoff * 2);
    const uint32_t offA1 = (uint32_t)((mw + 16 + aRow) * SROW + aKoff * 2);
    const int bRow  = wn * 32 + ((lane >> 4) * 8) + lrow;
    const int bKoff = ((lane >> 3) & 1) * 8;
    const uint32_t offB0 = (uint32_t)(bRow * SROW + bKoff * 2);
    const uint32_t offB1 = offB0 + 16 * SROW;

    float acc[4][2][4][4];
#pragma unroll
    for (int c = 0; c < 4; c++)
#pragma unroll
        for (int mt = 0; mt < 2; mt++)
#pragma unroll
            for (int nt = 0; nt < 4; nt++)
#pragma unroll
                for (int j = 0; j < 4; j++) acc[c][mt][nt][j] = 0.f;

    // ---- main loop: 8 phases (chunk = p>>1, kind = p&1: 0=Wh, 1=Wl) ----
#pragma unroll
    for (int p = 0; p < 8; p++) {
        const int c = p >> 1;
        const int kind = p & 1;
        cp_wait<0>();
        __syncthreads();

        const uint32_t b0a = sb + GB + offB0;
        const uint32_t b1a = sb + GB + offB1;
        const uint32_t ah0 = sb + GA_HI + offA0;
        const uint32_t ah1 = sb + GA_HI + offA1;
        const uint32_t al0 = sb + GA_LO + offA0;
        const uint32_t al1 = sb + GA_LO + offA1;

        if (kind == 0) {
#pragma unroll 4
            for (int ks = 0; ks < 16; ks++) {
                const uint32_t kb = (uint32_t)(ks * 32);
                uint32_t Ah0[4], Ah1[4], Al0[4], Al1[4], Bf0[4], Bf1[4];
                ldsm_x4(b0a + kb, Bf0[0], Bf0[1], Bf0[2], Bf0[3]);
                ldsm_x4(b1a + kb, Bf1[0], Bf1[1], Bf1[2], Bf1[3]);
                ldsm_x4(ah0 + kb, Ah0[0], Ah0[1], Ah0[2], Ah0[3]);
                ldsm_x4(ah1 + kb, Ah1[0], Ah1[1], Ah1[2], Ah1[3]);
                ldsm_x4(al0 + kb, Al0[0], Al0[1], Al0[2], Al0[3]);
                ldsm_x4(al1 + kb, Al1[0], Al1[1], Al1[2], Al1[3]);
#pragma unroll
                for (int nt = 0; nt < 4; nt++) {
                    uint32_t b0 = (nt < 2) ? Bf0[2 * nt]     : Bf1[2 * (nt - 2)];
                    uint32_t b1 = (nt < 2) ? Bf0[2 * nt + 1] : Bf1[2 * (nt - 2) + 1];
                    mma_bf16(acc[c][0][nt], Ah0, b0, b1);
                    mma_bf16(acc[c][1][nt], Ah1, b0, b1);
                    mma_bf16(acc[c][0][nt], Al0, b0, b1);
                    mma_bf16(acc[c][1][nt], Al1, b0, b1);
                }
            }
        } else {
#pragma unroll 4
            for (int ks = 0; ks < 16; ks++) {
                const uint32_t kb = (uint32_t)(ks * 32);
                uint32_t Ah0[4], Ah1[4], Bf0[4], Bf1[4];
                ldsm_x4(b0a + kb, Bf0[0], Bf0[1], Bf0[2], Bf0[3]);
                ldsm_x4(b1a + kb, Bf1[0], Bf1[1], Bf1[2], Bf1[3]);
                ldsm_x4(ah0 + kb, Ah0[0], Ah0[1], Ah0[2], Ah0[3]);
                ldsm_x4(ah1 + kb, Ah1[0], Ah1[1], Ah1[2], Ah1[3]);
#pragma unroll
                for (int nt = 0; nt < 4; nt++) {
                    uint32_t b0 = (nt < 2) ? Bf0[2 * nt]     : Bf1[2 * (nt - 2)];
                    uint32_t b1 = (nt < 2) ? Bf0[2 * nt + 1] : Bf1[2 * (nt - 2) + 1];
                    mma_bf16(acc[c][0][nt], Ah0, b0, b1);
                    mma_bf16(acc[c][1][nt], Ah1, b0, b1);
                }
            }
        }
        __syncthreads();                        // all warps done with B buffer

        if (p < 7) {
            const int pn = p + 1;
            const int cn = pn >> 1;
            const __nv_bfloat16* src = (pn & 1) ? g_Wl : g_Wh;
#pragma unroll
            for (int i = 0; i < 16; i++) {
                int idx = tid + i * 128;
                int r = idx >> 5, kc = idx & 31;
                cp_async16(sb + GB + (uint32_t)(r * SROW + kc * 16),
                           &src[(size_t)(cn * 64 + r) * KIN + kc * 8]);
            }
            cp_commit();
        }
    }

    // ---- LayerNorm stats (overlay B buffer region) ----
    float* sSum = (float*)(smem + GB);        // [64][2]
    float* sSq  = sSum + 128;                 // [64][2]
    float* sMu  = sSq + 128;                  // [64]
    float* sRs  = sMu + 64;                   // [64]

#pragma unroll
    for (int mt = 0; mt < 2; mt++)
#pragma unroll
        for (int half = 0; half < 2; half++) {
            float s = 0.f, q = 0.f;
#pragma unroll
            for (int c = 0; c < 4; c++)
#pragma unroll
                for (int nt = 0; nt < 4; nt++)
#pragma unroll
                    for (int j = 0; j < 2; j++) {
                        float v = acc[c][mt][nt][half * 2 + j];
                        s += v; q += v * v;
                    }
            s += __shfl_xor_sync(0xffffffffu, s, 1);
            q += __shfl_xor_sync(0xffffffffu, q, 1);
            s += __shfl_xor_sync(0xffffffffu, s, 2);
            q += __shfl_xor_sync(0xffffffffu, q, 2);
            if (tig == 0) {
                int row = mw + mt * 16 + half * 8 + g;
                sSum[row * 2 + wn] = s;
                sSq[row * 2 + wn]  = q;
            }
        }
    __syncthreads();

    if (tid < 64) {
        float s = sSum[tid * 2] + sSum[tid * 2 + 1];
        float q = sSq[tid * 2] + sSq[tid * 2 + 1];
        float mu = s * (1.0f / OD);
        float var = fmaxf(q * (1.0f / OD) - mu * mu, 0.0f);
        sMu[tid] = mu;
        sRs[tid] = rsqrtf(var + LN_EPS);
    }
    __syncthreads();

    // ---- normalize + affine + ReLU + store ----
#pragma unroll
    for (int mt = 0; mt < 2; mt++)
#pragma unroll
        for (int half = 0; half < 2; half++) {
            int row = mw + mt * 16 + half * 8 + g;
            float mu = sMu[row];
            float rs = sRs[row];
            float* orow = out + (size_t)(rowBase + row) * OD;
#pragma unroll
            for (int c = 0; c < 4; c++)
#pragma unroll
                for (int nt = 0; nt < 4; nt++) {
                    int col = c * 64 + wn * 32 + nt * 8 + tig * 2;
                    float2 gb0 = *(const float2*)&gamma[col];
                    float2 bb0 = *(const float2*)&beta[col];
                    float v0 = acc[c][mt][nt][half * 2 + 0];
                    float v1 = acc[c][mt][nt][half * 2 + 1];
                    float2 r2;
                    r2.x = fmaxf((v0 - mu) * rs * gb0.x + bb0.x, 0.0f);
                    r2.y = fmaxf((v1 - mu) * rs * gb0.y + bb0.y, 0.0f);
                    *(float2*)&orow[col] = r2;
                }
        }
}

// ---------------------------------------------------------------------------
extern "C" void kernel_launch(void* const* d_in, const int* in_sizes, int n_in,
                              void* d_out, int out_size)
{
    const float* pos_x   = (const float*)d_in[0];
    const float* xfeat   = (const float*)d_in[1];
    const int*   batch_x = (const int*)  d_in[2];
    const float* pos_y   = (const float*)d_in[3];
    const float* yfeat   = (const float*)d_in[4];
    const int*   batch_y = (const int*)  d_in[5];
    const float* W       = (const float*)d_in[6];
    const float* gamma   = (const float*)d_in[7];
    const float* beta    = (const float*)d_in[8];
    float* out = (float*)d_out;

    prep_kernel<<<KNN_BLOCKS + W_BLOCKS, 256>>>(pos_x, xfeat, batch_x,
                                                pos_y, yfeat, batch_y, W);

    cudaFuncSetAttribute(gemm_mma_kernel,
                         cudaFuncAttributeMaxDynamicSharedMemorySize, G_TOTAL);
    gemm_mma_kernel<<<NY / 64, 128, G_TOTAL>>>(gamma, beta, out);
}

// round 7
// speedup vs baseline: 1.0886x; 1.0317x over previous
#include <cuda_runtime.h>
#include <cuda_bf16.h>
#include <cstdint>
#include <math.h>

// Problem shapes (fixed)
#define NX 4096
#define NY 16384
#define CX 128
#define CY 128
#define OD 256
#define KIN 256
#define BIGD 1e30f
#define W_EPS 1e-16f
#define LN_EPS 1e-5f

// Global scratch: pre-split A (concat(interp|y)) and W, bf16 hi/lo
__device__ __nv_bfloat16 g_Ah[NY * KIN];
__device__ __nv_bfloat16 g_Al[NY * KIN];
__device__ __nv_bfloat16 g_Wh[OD * KIN];
__device__ __nv_bfloat16 g_Wl[OD * KIN];

// ---------------------------------------------------------------------------
// Helpers (baseline PTX, valid for compute_100)
// ---------------------------------------------------------------------------
static __device__ __forceinline__ uint32_t smem_u32(const void* p) {
    uint32_t a;
    asm("{ .reg .u64 t; cvta.to.shared.u64 t, %1; cvt.u32.u64 %0, t; }"
        : "=r"(a) : "l"(p));
    return a;
}

static __device__ __forceinline__ void ldsm_x4(uint32_t addr, uint32_t* r) {
    asm volatile("ldmatrix.sync.aligned.m8n8.x4.shared.b16 {%0,%1,%2,%3}, [%4];"
                 : "=r"(r[0]), "=r"(r[1]), "=r"(r[2]), "=r"(r[3]) : "r"(addr));
}

static __device__ __forceinline__ void mma_bf16(float* d, const uint32_t* a,
                                                uint32_t b0, uint32_t b1) {
    asm volatile(
        "mma.sync.aligned.m16n8k16.row.col.f32.bf16.bf16.f32 "
        "{%0,%1,%2,%3},{%4,%5,%6,%7},{%8,%9},{%0,%1,%2,%3};"
        : "+f"(d[0]), "+f"(d[1]), "+f"(d[2]), "+f"(d[3])
        : "r"(a[0]), "r"(a[1]), "r"(a[2]), "r"(a[3]), "r"(b0), "r"(b1));
}

static __device__ __forceinline__ void cp_async16(uint32_t dst, const void* src) {
    asm volatile("cp.async.cg.shared.global [%0], [%1], 16;" :: "r"(dst), "l"(src));
}
static __device__ __forceinline__ void cp_commit() {
    asm volatile("cp.async.commit_group;" ::: "memory");
}
template <int N>
static __device__ __forceinline__ void cp_wait() {
    asm volatile("cp.async.wait_group %0;" :: "n"(N) : "memory");
}

// Fast hi/lo bf16 split of a float pair:
//   hi = truncate-to-bf16 (PRMT picks top 2 bytes of each) — exact bits
//   lo = bf16_rn(v - hi)  (v - hi is exact in f32)
static __device__ __forceinline__ void split_pair(float v0, float v1,
                                                  uint32_t& hp, uint32_t& lp) {
    uint32_t u0 = __float_as_uint(v0), u1 = __float_as_uint(v1);
    asm("prmt.b32 %0, %1, %2, 0x7632;" : "=r"(hp) : "r"(u0), "r"(u1));
    float h0 = __uint_as_float(u0 & 0xFFFF0000u);
    float h1 = __uint_as_float(u1 & 0xFFFF0000u);
    float l0 = v0 - h0, l1 = v1 - h1;
    asm("cvt.rn.bf16x2.f32 %0, %1, %2;" : "=r"(lp) : "f"(l1), "f"(l0));
}

// Branchless lexicographic top-3 insert
#define BINSERT(dd, jj)                                                         \
    do {                                                                        \
        float _d = (dd); int _j = (jj);                                         \
        bool lt0 = (_d < d0) || (_d == d0 && _j < i0);                          \
        bool lt1 = (_d < d1) || (_d == d1 && _j < i1);                          \
        bool lt2 = (_d < d2v) || (_d == d2v && _j < i2);                        \
        d2v = lt1 ? d1 : (lt2 ? _d : d2v); i2 = lt1 ? i1 : (lt2 ? _j : i2);     \
        d1  = lt0 ? d0 : (lt1 ? _d : d1);  i1 = lt0 ? i0 : (lt1 ? _j : i1);     \
        d0  = lt0 ? _d : d0;               i0 = lt0 ? _j : i0;                  \
    } while (0)

// ---------------------------------------------------------------------------
// Kernel 1: KNN + interpolation + A/W bf16 hi-lo pre-split
// ---------------------------------------------------------------------------
#define KNN_BLOCKS 2048
#define W_BLOCKS 32
#define MAXP 2048

__global__ void prep_kernel(const float* __restrict__ pos_x,
                            const float* __restrict__ xfeat,
                            const int*   __restrict__ batch_x,
                            const float* __restrict__ pos_y,
                            const float* __restrict__ yfeat,
                            const int*   __restrict__ batch_y,
                            const float* __restrict__ W)
{
    if (blockIdx.x >= KNN_BLOCKS) {
        int base = ((int)blockIdx.x - KNN_BLOCKS) * (256 * 4) + threadIdx.x;
        uint32_t* wh = (uint32_t*)g_Wh;
        uint32_t* wl = (uint32_t*)g_Wl;
#pragma unroll
        for (int i = 0; i < 4; i++) {
            int p = base + i * 256;
            float2 v = *(const float2*)&W[p * 2];
            split_pair(v.x, v.y, wh[p], wl[p]);
        }
        return;
    }

    __shared__ float spx[MAXP], spy[MAXP], spz[MAXP], snrm[MAXP];
    __shared__ int sbounds[9];

    const int tid = threadIdx.x;
    if (tid < 9) {
        int t = tid;
        int lo = 0, hi = NX;
        while (lo < hi) { int m = (lo + hi) >> 1; if (batch_x[m] < t) lo = m + 1; else hi = m; }
        sbounds[t] = lo;
    }
    __syncthreads();

    const int q0   = blockIdx.x * 8;
    const int bmin = batch_y[q0];
    const int bmax = batch_y[q0 + 7];
    const int s0   = sbounds[bmin];
    const int e1   = sbounds[bmax + 1];
    const int n    = e1 - s0;
    const bool useSmem = (n <= MAXP);

    if (useSmem) {
        for (int i = tid; i < n; i += 256) {
            int j = s0 + i;
            float x = pos_x[j * 3 + 0];
            float y = pos_x[j * 3 + 1];
            float z = pos_x[j * 3 + 2];
            spx[i] = x; spy[i] = y; spz[i] = z;
            snrm[i] = x * x + y * y + z * z;
        }
    }
    __syncthreads();

    const int lane = tid & 31;
    const int yi   = q0 + (tid >> 5);

    const float py0 = pos_y[yi * 3 + 0];
    const float py1 = pos_y[yi * 3 + 1];
    const float py2 = pos_y[yi * 3 + 2];
    const float ny2 = py0 * py0 + py1 * py1 + py2 * py2;
    const int b = batch_y[yi];
    const int s = sbounds[b];
    const int e = sbounds[b + 1];

    float d0 = BIGD, d1 = BIGD, d2v = BIGD;
    int   i0 = 0,    i1 = 0,    i2 = 0;

    if (useSmem) {
        const int ls = s - s0, le = e - s0;
        for (int jl = ls + lane; jl < le; jl += 32) {
            float dot = py0 * spx[jl] + py1 * spy[jl] + py2 * spz[jl];
            float d = fmaxf(ny2 + snrm[jl] - 2.0f * dot, 0.0f);
            BINSERT(d, s0 + jl);
        }
    } else {
        for (int j = s + lane; j < e; j += 32) {
            float px0 = pos_x[j * 3 + 0];
            float px1 = pos_x[j * 3 + 1];
            float px2 = pos_x[j * 3 + 2];
            float nx2 = px0 * px0 + px1 * px1 + px2 * px2;
            float dot = py0 * px0 + py1 * px1 + py2 * px2;
            float d = fmaxf(ny2 + nx2 - 2.0f * dot, 0.0f);
            BINSERT(d, j);
        }
    }

    for (int off = 16; off; off >>= 1) {
        float od0 = __shfl_xor_sync(0xffffffffu, d0,  off);
        float od1 = __shfl_xor_sync(0xffffffffu, d1,  off);
        float od2 = __shfl_xor_sync(0xffffffffu, d2v, off);
        int   oi0 = __shfl_xor_sync(0xffffffffu, i0,  off);
        int   oi1 = __shfl_xor_sync(0xffffffffu, i1,  off);
        int   oi2 = __shfl_xor_sync(0xffffffffu, i2,  off);
        BINSERT(od0, oi0);
        BINSERT(od1, oi1);
        BINSERT(od2, oi2);
    }

    const float w0 = 1.0f / fmaxf(d0,  W_EPS);
    const float w1 = 1.0f / fmaxf(d1,  W_EPS);
    const float w2 = 1.0f / fmaxf(d2v, W_EPS);
    const float inv_wsum = 1.0f / (w0 + w1 + w2);

    const float* f0 = xfeat + (size_t)i0 * CX;
    const float* f1 = xfeat + (size_t)i1 * CX;
    const float* f2 = xfeat + (size_t)i2 * CX;
    const float* fy = yfeat + (size_t)yi * CY;
    uint2* ah = (uint2*)(g_Ah + (size_t)yi * KIN);
    uint2* al = (uint2*)(g_Al + (size_t)yi * KIN);

    {
        int c = lane * 4;
        float4 a0 = *(const float4*)&f0[c];
        float4 a1 = *(const float4*)&f1[c];
        float4 a2 = *(const float4*)&f2[c];
        float4 ay = *(const float4*)&fy[c];
        float v0 = (w0 * a0.x + w1 * a1.x + w2 * a2.x) * inv_wsum;
        float v1 = (w0 * a0.y + w1 * a1.y + w2 * a2.y) * inv_wsum;
        float v2 = (w0 * a0.z + w1 * a1.z + w2 * a2.z) * inv_wsum;
        float v3 = (w0 * a0.w + w1 * a1.w + w2 * a2.w) * inv_wsum;
        uint2 hp, lp;
        split_pair(v0, v1, hp.x, lp.x);
        split_pair(v2, v3, hp.y, lp.y);
        ah[lane] = hp; al[lane] = lp;
        split_pair(ay.x, ay.y, hp.x, lp.x);
        split_pair(ay.z, ay.w, hp.y, lp.y);
        ah[32 + lane] = hp; al[32 + lane] = lp;
    }
}

// ---------------------------------------------------------------------------
// Kernel 2: bf16 hi/lo-split mma.sync GEMM + LN + ReLU, K-streamed
// Per CTA: 128 rows x 256 cols (full N -> fused LN). 256 threads = 8 warps
// (2m x 4n); warp tile 64m x 64n. K in 4 chunks of 64, double-buffered.
// Per k16 per warp: 16 LDSM.x4 (8 KB) -> 96 MMA  = 85 B/MMA.
// SMEM per chunk buffer (stride 144 B = 64 bf16 + 16 pad):
//   A_hi[128][144] @0      (18432)
//   A_lo          @18432
//   B_hi[256][144] @36864  (36864)
//   B_lo          @73728
// buffer = 110592 B, x2 = 221184 B
// ---------------------------------------------------------------------------
#define CH 144
#define O_AH 0
#define O_AL 18432
#define O_BH 36864
#define O_BL 73728
#define BUF 110592
#define G_TOTAL 221184

__global__ __launch_bounds__(256, 1)
void gemm_mma_kernel(const float* __restrict__ gamma,
                     const float* __restrict__ beta,
                     float* __restrict__ out)
{
    extern __shared__ char smem[];
    const uint32_t sb = smem_u32(smem);

    const int tid  = threadIdx.x;
    const int wid  = tid >> 5;
    const int lane = tid & 31;
    const int g    = lane >> 2;
    const int tig  = lane & 3;
    const int mw   = (wid >> 2) * 64;      // warp row base (0/64)
    const int nw   = wid & 3;              // warp col base = nw*64
    const int rowBase = blockIdx.x * 128;

    // ---- chunk loader (ck = k-chunk 0..3) ----
    auto load_chunk = [&](int ck, uint32_t bb) {
        const int kof = ck * 64;
#pragma unroll
        for (int i = 0; i < 4; i++) {          // A: 1024 16B-chunks
            int idx = tid + i * 256;
            int r = idx >> 3, kc = idx & 7;
            const size_t gs = (size_t)(rowBase + r) * KIN + kof + kc * 8;
            uint32_t off = (uint32_t)(r * CH + kc * 16);
            cp_async16(bb + O_AH + off, &g_Ah[gs]);
            cp_async16(bb + O_AL + off, &g_Al[gs]);
        }
#pragma unroll
        for (int i = 0; i < 8; i++) {          // B: 2048 16B-chunks
            int idx = tid + i * 256;
            int r = idx >> 3, kc = idx & 7;
            const size_t gs = (size_t)r * KIN + kof + kc * 8;
            uint32_t off = (uint32_t)(r * CH + kc * 16);
            cp_async16(bb + O_BH + off, &g_Wh[gs]);
            cp_async16(bb + O_BL + off, &g_Wl[gs]);
        }
        cp_commit();
    };

    load_chunk(0, sb);

    // ---- per-lane ldmatrix offsets ----
    const int quad  = lane >> 3;
    const int lrow  = lane & 7;
    const int aRow  = (quad & 1) * 8 + lrow;
    const int aKoff = (quad >> 1) * 8;
    const int bRow  = ((lane >> 4) * 8) + lrow;
    const int bKoff = ((lane >> 3) & 1) * 8;

    float acc[4][8][4];
#pragma unroll
    for (int mt = 0; mt < 4; mt++)
#pragma unroll
        for (int nt = 0; nt < 8; nt++)
#pragma unroll
            for (int j = 0; j < 4; j++) acc[mt][nt][j] = 0.f;

    // ---- main loop over 4 k-chunks ----
#pragma unroll 1
    for (int ck = 0; ck < 4; ck++) {
        if (ck < 3) {
            load_chunk(ck + 1, sb + (uint32_t)((ck + 1) & 1) * BUF);
            cp_wait<1>();
        } else {
            cp_wait<0>();
        }
        __syncthreads();

        const uint32_t bb = sb + (uint32_t)(ck & 1) * BUF;
        const uint32_t aBase = bb + O_AH + (uint32_t)((mw + aRow) * CH + aKoff * 2);
        const uint32_t bBase = bb + O_BH + (uint32_t)((nw * 64 + bRow) * CH + bKoff * 2);

#pragma unroll
        for (int ks = 0; ks < 4; ks++) {
            const uint32_t kb = (uint32_t)(ks * 32);
            uint32_t Bh[16], Bl[16];
#pragma unroll
            for (int i = 0; i < 4; i++) {
                uint32_t ba = bBase + (uint32_t)(i * 16 * CH) + kb;
                ldsm_x4(ba, &Bh[i * 4]);
                ldsm_x4(ba + (O_BL - O_BH), &Bl[i * 4]);
            }
#pragma unroll
            for (int mt = 0; mt < 4; mt++) {
                uint32_t Ah[4], Al[4];
                uint32_t aa = aBase + (uint32_t)(mt * 16 * CH) + kb;
                ldsm_x4(aa, Ah);
                ldsm_x4(aa + (O_AL - O_AH), Al);
#pragma unroll
                for (int nt = 0; nt < 8; nt++) {
                    uint32_t b0 = Bh[2 * nt], b1 = Bh[2 * nt + 1];
                    mma_bf16(acc[mt][nt], Ah, b0, b1);
                    mma_bf16(acc[mt][nt], Al, b0, b1);
                    mma_bf16(acc[mt][nt], Ah, Bl[2 * nt], Bl[2 * nt + 1]);
                }
            }
        }
        __syncthreads();
    }

    // ---- LayerNorm stats (overlay smem) ----
    float* sSum = (float*)smem;               // [128][4]
    float* sSq  = sSum + 512;                 // [128][4]
    float* sMu  = sSq + 512;                  // [128]
    float* sRs  = sMu + 128;                  // [128]

#pragma unroll
    for (int mt = 0; mt < 4; mt++)
#pragma unroll
        for (int half = 0; half < 2; half++) {
            float s = 0.f, q = 0.f;
#pragma unroll
            for (int nt = 0; nt < 8; nt++)
#pragma unroll
                for (int j = 0; j < 2; j++) {
                    float v = acc[mt][nt][half * 2 + j];
                    s += v; q += v * v;
                }
            s += __shfl_xor_sync(0xffffffffu, s, 1);
            q += __shfl_xor_sync(0xffffffffu, q, 1);
            s += __shfl_xor_sync(0xffffffffu, s, 2);
            q += __shfl_xor_sync(0xffffffffu, q, 2);
            if (tig == 0) {
                int row = mw + mt * 16 + half * 8 + g;
                sSum[row * 4 + nw] = s;
                sSq[row * 4 + nw]  = q;
            }
        }
    __syncthreads();

    if (tid < 128) {
        float s = sSum[tid * 4] + sSum[tid * 4 + 1] + sSum[tid * 4 + 2] + sSum[tid * 4 + 3];
        float q = sSq[tid * 4] + sSq[tid * 4 + 1] + sSq[tid * 4 + 2] + sSq[tid * 4 + 3];
        float mu = s * (1.0f / OD);
        float var = fmaxf(q * (1.0f / OD) - mu * mu, 0.0f);
        sMu[tid] = mu;
        sRs[tid] = rsqrtf(var + LN_EPS);
    }
    __syncthreads();

    // ---- normalize + affine + ReLU + store ----
#pragma unroll
    for (int mt = 0; mt < 4; mt++)
#pragma unroll
        for (int half = 0; half < 2; half++) {
            int row = mw + mt * 16 + half * 8 + g;
            float mu = sMu[row];
            float rs = sRs[row];
            float* orow = out + (size_t)(rowBase + row) * OD;
#pragma unroll
            for (int nt = 0; nt < 8; nt++) {
                int col = nw * 64 + nt * 8 + tig * 2;
                float2 gb0 = *(const float2*)&gamma[col];
                float2 bb0 = *(const float2*)&beta[col];
                float v0 = acc[mt][nt][half * 2 + 0];
                float v1 = acc[mt][nt][half * 2 + 1];
                float2 r2;
                r2.x = fmaxf((v0 - mu) * rs * gb0.x + bb0.x, 0.0f);
                r2.y = fmaxf((v1 - mu) * rs * gb0.y + bb0.y, 0.0f);
                *(float2*)&orow[col] = r2;
            }
        }
}

// ---------------------------------------------------------------------------
extern "C" void kernel_launch(void* const* d_in, const int* in_sizes, int n_in,
                              void* d_out, int out_size)
{
    const float* pos_x   = (const float*)d_in[0];
    const float* xfeat   = (const float*)d_in[1];
    const int*   batch_x = (const int*)  d_in[2];
    const float* pos_y   = (const float*)d_in[3];
    const float* yfeat   = (const float*)d_in[4];
    const int*   batch_y = (const int*)  d_in[5];
    const float* W       = (const float*)d_in[6];
    const float* gamma   = (const float*)d_in[7];
    const float* beta    = (const float*)d_in[8];
    float* out = (float*)d_out;

    prep_kernel<<<KNN_BLOCKS + W_BLOCKS, 256>>>(pos_x, xfeat, batch_x,
                                                pos_y, yfeat, batch_y, W);

    cudaFuncSetAttribute(gemm_mma_kernel,
                         cudaFuncAttributeMaxDynamicSharedMemorySize, G_TOTAL);
    gemm_mma_kernel<<<NY / 128, 256, G_TOTAL>>>(gamma, beta, out);
}

// round 8
// speedup vs baseline: 1.2284x; 1.1284x over previous
#include <cuda_runtime.h>
#include <cuda_bf16.h>
#include <cstdint>
#include <math.h>

// Problem shapes (fixed)
#define NX 4096
#define NY 16384
#define CX 128
#define CY 128
#define OD 256
#define KIN 256
#define BIGD 1e30f
#define W_EPS 1e-16f
#define LN_EPS 1e-5f

// Global scratch: pre-split A (concat(interp|y)) and W, bf16 hi/lo
__device__ __nv_bfloat16 g_Ah[NY * KIN];
__device__ __nv_bfloat16 g_Al[NY * KIN];
__device__ __nv_bfloat16 g_Wh[OD * KIN];
__device__ __nv_bfloat16 g_Wl[OD * KIN];

// ---------------------------------------------------------------------------
// Helpers (baseline PTX, valid for compute_100)
// ---------------------------------------------------------------------------
static __device__ __forceinline__ uint32_t smem_u32(const void* p) {
    uint32_t a;
    asm("{ .reg .u64 t; cvta.to.shared.u64 t, %1; cvt.u32.u64 %0, t; }"
        : "=r"(a) : "l"(p));
    return a;
}

static __device__ __forceinline__ void ldsm_x4(uint32_t addr, uint32_t* r) {
    asm volatile("ldmatrix.sync.aligned.m8n8.x4.shared.b16 {%0,%1,%2,%3}, [%4];"
                 : "=r"(r[0]), "=r"(r[1]), "=r"(r[2]), "=r"(r[3]) : "r"(addr));
}

static __device__ __forceinline__ void mma_bf16(float* d, const uint32_t* a,
                                                uint32_t b0, uint32_t b1) {
    asm volatile(
        "mma.sync.aligned.m16n8k16.row.col.f32.bf16.bf16.f32 "
        "{%0,%1,%2,%3},{%4,%5,%6,%7},{%8,%9},{%0,%1,%2,%3};"
        : "+f"(d[0]), "+f"(d[1]), "+f"(d[2]), "+f"(d[3])
        : "r"(a[0]), "r"(a[1]), "r"(a[2]), "r"(a[3]), "r"(b0), "r"(b1));
}

static __device__ __forceinline__ void cp_async16(uint32_t dst, const void* src) {
    asm volatile("cp.async.cg.shared.global [%0], [%1], 16;" :: "r"(dst), "l"(src));
}
static __device__ __forceinline__ void cp_commit() {
    asm volatile("cp.async.commit_group;" ::: "memory");
}
template <int N>
static __device__ __forceinline__ void cp_wait() {
    asm volatile("cp.async.wait_group %0;" :: "n"(N) : "memory");
}

// Fast hi/lo bf16 split of a float pair
static __device__ __forceinline__ void split_pair(float v0, float v1,
                                                  uint32_t& hp, uint32_t& lp) {
    uint32_t u0 = __float_as_uint(v0), u1 = __float_as_uint(v1);
    asm("prmt.b32 %0, %1, %2, 0x7632;" : "=r"(hp) : "r"(u0), "r"(u1));
    float h0 = __uint_as_float(u0 & 0xFFFF0000u);
    float h1 = __uint_as_float(u1 & 0xFFFF0000u);
    float l0 = v0 - h0, l1 = v1 - h1;
    asm("cvt.rn.bf16x2.f32 %0, %1, %2;" : "=r"(lp) : "f"(l1), "f"(l0));
}

// Branchless top-3 insert (distance only; FP ties are measure-zero)
#define BINSERT(dd, jj)                                                         \
    do {                                                                        \
        float _d = (dd); int _j = (jj);                                         \
        bool lt0 = _d < d0;                                                     \
        bool lt1 = _d < d1;                                                     \
        bool lt2 = _d < d2v;                                                    \
        d2v = lt1 ? d1 : (lt2 ? _d : d2v); i2 = lt1 ? i1 : (lt2 ? _j : i2);     \
        d1  = lt0 ? d0 : (lt1 ? _d : d1);  i1 = lt0 ? i0 : (lt1 ? _j : i1);     \
        d0  = lt0 ? _d : d0;               i0 = lt0 ? _j : i0;                  \
    } while (0)

// ---------------------------------------------------------------------------
// Kernel 1: KNN + interpolation + A/W bf16 hi-lo pre-split
// ---------------------------------------------------------------------------
#define KNN_BLOCKS 2048
#define W_BLOCKS 32
#define MAXP 2048

__global__ __launch_bounds__(256)
void prep_kernel(const float* __restrict__ pos_x,
                 const float* __restrict__ xfeat,
                 const int*   __restrict__ batch_x,
                 const float* __restrict__ pos_y,
                 const float* __restrict__ yfeat,
                 const int*   __restrict__ batch_y,
                 const float* __restrict__ W)
{
    if (blockIdx.x >= KNN_BLOCKS) {
        int base = ((int)blockIdx.x - KNN_BLOCKS) * (256 * 4) + threadIdx.x;
        uint32_t* wh = (uint32_t*)g_Wh;
        uint32_t* wl = (uint32_t*)g_Wl;
#pragma unroll
        for (int i = 0; i < 4; i++) {
            int p = base + i * 256;
            float2 v = *(const float2*)&W[p * 2];
            split_pair(v.x, v.y, wh[p], wl[p]);
        }
        return;
    }

    __shared__ float spx[MAXP], spy[MAXP], spz[MAXP], snrm[MAXP];
    __shared__ int sbounds[9];

    const int tid = threadIdx.x;
    if (tid < 9) {
        int t = tid;
        int lo = 0, hi = NX;
        while (lo < hi) { int m = (lo + hi) >> 1; if (batch_x[m] < t) lo = m + 1; else hi = m; }
        sbounds[t] = lo;
    }
    __syncthreads();

    const int q0   = blockIdx.x * 8;
    const int bmin = batch_y[q0];
    const int bmax = batch_y[q0 + 7];
    const int s0   = sbounds[bmin];
    const int e1   = sbounds[bmax + 1];
    const int n    = e1 - s0;
    const bool useSmem = (n <= MAXP);

    if (useSmem) {
        for (int i = tid; i < n; i += 256) {
            int j = s0 + i;
            float x = pos_x[j * 3 + 0];
            float y = pos_x[j * 3 + 1];
            float z = pos_x[j * 3 + 2];
            spx[i] = x; spy[i] = y; spz[i] = z;
            snrm[i] = x * x + y * y + z * z;
        }
    }
    __syncthreads();

    const int lane = tid & 31;
    const int yi   = q0 + (tid >> 5);

    const float py0 = pos_y[yi * 3 + 0];
    const float py1 = pos_y[yi * 3 + 1];
    const float py2 = pos_y[yi * 3 + 2];
    const float ny2 = py0 * py0 + py1 * py1 + py2 * py2;
    const int b = batch_y[yi];
    const int s = sbounds[b];
    const int e = sbounds[b + 1];

    float d0 = BIGD, d1 = BIGD, d2v = BIGD;
    int   i0 = 0,    i1 = 0,    i2 = 0;

    if (useSmem) {
        const int ls = s - s0, le = e - s0;
        for (int jl = ls + lane; jl < le; jl += 32) {
            float dot = py0 * spx[jl] + py1 * spy[jl] + py2 * spz[jl];
            float d = fmaxf(ny2 + snrm[jl] - 2.0f * dot, 0.0f);
            BINSERT(d, s0 + jl);
        }
    } else {
        for (int j = s + lane; j < e; j += 32) {
            float px0 = pos_x[j * 3 + 0];
            float px1 = pos_x[j * 3 + 1];
            float px2 = pos_x[j * 3 + 2];
            float nx2 = px0 * px0 + px1 * px1 + px2 * px2;
            float dot = py0 * px0 + py1 * px1 + py2 * px2;
            float d = fmaxf(ny2 + nx2 - 2.0f * dot, 0.0f);
            BINSERT(d, j);
        }
    }

    for (int off = 16; off; off >>= 1) {
        float od0 = __shfl_xor_sync(0xffffffffu, d0,  off);
        float od1 = __shfl_xor_sync(0xffffffffu, d1,  off);
        float od2 = __shfl_xor_sync(0xffffffffu, d2v, off);
        int   oi0 = __shfl_xor_sync(0xffffffffu, i0,  off);
        int   oi1 = __shfl_xor_sync(0xffffffffu, i1,  off);
        int   oi2 = __shfl_xor_sync(0xffffffffu, i2,  off);
        BINSERT(od0, oi0);
        BINSERT(od1, oi1);
        BINSERT(od2, oi2);
    }

    const float w0 = 1.0f / fmaxf(d0,  W_EPS);
    const float w1 = 1.0f / fmaxf(d1,  W_EPS);
    const float w2 = 1.0f / fmaxf(d2v, W_EPS);
    const float inv_wsum = 1.0f / (w0 + w1 + w2);

    const float* f0 = xfeat + (size_t)i0 * CX;
    const float* f1 = xfeat + (size_t)i1 * CX;
    const float* f2 = xfeat + (size_t)i2 * CX;
    const float* fy = yfeat + (size_t)yi * CY;
    uint2* ah = (uint2*)(g_Ah + (size_t)yi * KIN);
    uint2* al = (uint2*)(g_Al + (size_t)yi * KIN);

    {
        int c = lane * 4;
        float4 a0 = *(const float4*)&f0[c];
        float4 a1 = *(const float4*)&f1[c];
        float4 a2 = *(const float4*)&f2[c];
        float4 ay = *(const float4*)&fy[c];
        float v0 = (w0 * a0.x + w1 * a1.x + w2 * a2.x) * inv_wsum;
        float v1 = (w0 * a0.y + w1 * a1.y + w2 * a2.y) * inv_wsum;
        float v2 = (w0 * a0.z + w1 * a1.z + w2 * a2.z) * inv_wsum;
        float v3 = (w0 * a0.w + w1 * a1.w + w2 * a2.w) * inv_wsum;
        uint2 hp, lp;
        split_pair(v0, v1, hp.x, lp.x);
        split_pair(v2, v3, hp.y, lp.y);
        ah[lane] = hp; al[lane] = lp;
        split_pair(ay.x, ay.y, hp.x, lp.x);
        split_pair(ay.z, ay.w, hp.y, lp.y);
        ah[32 + lane] = hp; al[32 + lane] = lp;
    }
}

// ---------------------------------------------------------------------------
// Kernel 2: bf16 hi/lo-split mma.sync GEMM + LN + ReLU, K-streamed
// Per CTA: 128 rows x 256 cols. 512 threads = 16 warps (2m x 8n);
// warp tile 64m x 32n -> acc 64 regs/thread, 4 warps/SMSP for latency hiding.
// K in 4 chunks of 64, double-buffered.
// SMEM per chunk buffer (stride 144 B):
//   A_hi[128][144] @0, A_lo @18432, B_hi[256][144] @36864, B_lo @73728
// buffer = 110592 B, x2 = 221184 B
// ---------------------------------------------------------------------------
#define CH 144
#define O_AH 0
#define O_AL 18432
#define O_BH 36864
#define O_BL 73728
#define BUF 110592
#define G_TOTAL 221184

__global__ __launch_bounds__(512, 1)
void gemm_mma_kernel(const float* __restrict__ gamma,
                     const float* __restrict__ beta,
                     float* __restrict__ out)
{
    extern __shared__ char smem[];
    const uint32_t sb = smem_u32(smem);

    const int tid  = threadIdx.x;
    const int wid  = tid >> 5;
    const int lane = tid & 31;
    const int g    = lane >> 2;
    const int tig  = lane & 3;
    const int mw   = (wid >> 3) * 64;      // warp row base (0/64)
    const int nw   = wid & 7;              // warp col base = nw*32
    const int rowBase = blockIdx.x * 128;

    // ---- chunk loader ----
    auto load_chunk = [&](int ck, uint32_t bb) {
        const int kof = ck * 64;
#pragma unroll
        for (int i = 0; i < 2; i++) {          // A: 1024 16B-chunks (hi+lo)
            int idx = tid + i * 512;
            int r = idx >> 3, kc = idx & 7;
            const size_t gs = (size_t)(rowBase + r) * KIN + kof + kc * 8;
            uint32_t off = (uint32_t)(r * CH + kc * 16);
            cp_async16(bb + O_AH + off, &g_Ah[gs]);
            cp_async16(bb + O_AL + off, &g_Al[gs]);
        }
#pragma unroll
        for (int i = 0; i < 4; i++) {          // B: 2048 16B-chunks (hi+lo)
            int idx = tid + i * 512;
            int r = idx >> 3, kc = idx & 7;
            const size_t gs = (size_t)r * KIN + kof + kc * 8;
            uint32_t off = (uint32_t)(r * CH + kc * 16);
            cp_async16(bb + O_BH + off, &g_Wh[gs]);
            cp_async16(bb + O_BL + off, &g_Wl[gs]);
        }
        cp_commit();
    };

    load_chunk(0, sb);

    // ---- per-lane ldmatrix offsets ----
    const int quad  = lane >> 3;
    const int lrow  = lane & 7;
    const int aRow  = (quad & 1) * 8 + lrow;
    const int aKoff = (quad >> 1) * 8;
    const int bRow  = ((lane >> 4) * 8) + lrow;
    const int bKoff = ((lane >> 3) & 1) * 8;

    float acc[4][4][4];
#pragma unroll
    for (int mt = 0; mt < 4; mt++)
#pragma unroll
        for (int nt = 0; nt < 4; nt++)
#pragma unroll
            for (int j = 0; j < 4; j++) acc[mt][nt][j] = 0.f;

    // ---- main loop over 4 k-chunks ----
#pragma unroll 1
    for (int ck = 0; ck < 4; ck++) {
        if (ck < 3) {
            load_chunk(ck + 1, sb + (uint32_t)((ck + 1) & 1) * BUF);
            cp_wait<1>();
        } else {
            cp_wait<0>();
        }
        __syncthreads();

        const uint32_t bb = sb + (uint32_t)(ck & 1) * BUF;
        const uint32_t aBase = bb + O_AH + (uint32_t)((mw + aRow) * CH + aKoff * 2);
        const uint32_t bBase = bb + O_BH + (uint32_t)((nw * 32 + bRow) * CH + bKoff * 2);

#pragma unroll
        for (int ks = 0; ks < 4; ks++) {
            const uint32_t kb = (uint32_t)(ks * 32);
            uint32_t Bh[8], Bl[8];
#pragma unroll
            for (int i = 0; i < 2; i++) {
                uint32_t ba = bBase + (uint32_t)(i * 16 * CH) + kb;
                ldsm_x4(ba, &Bh[i * 4]);
                ldsm_x4(ba + (O_BL - O_BH), &Bl[i * 4]);
            }
#pragma unroll
            for (int mt = 0; mt < 4; mt++) {
                uint32_t Ah[4], Al[4];
                uint32_t aa = aBase + (uint32_t)(mt * 16 * CH) + kb;
                ldsm_x4(aa, Ah);
                ldsm_x4(aa + (O_AL - O_AH), Al);
#pragma unroll
                for (int nt = 0; nt < 4; nt++) {
                    uint32_t b0 = Bh[2 * nt], b1 = Bh[2 * nt + 1];
                    mma_bf16(acc[mt][nt], Ah, b0, b1);
                    mma_bf16(acc[mt][nt], Al, b0, b1);
                    mma_bf16(acc[mt][nt], Ah, Bl[2 * nt], Bl[2 * nt + 1]);
                }
            }
        }
        __syncthreads();
    }

    // ---- LayerNorm stats (overlay smem) ----
    float* sSum = (float*)smem;               // [128][8]
    float* sSq  = sSum + 1024;                // [128][8]
    float* sMu  = sSq + 1024;                 // [128]
    float* sRs  = sMu + 128;                  // [128]

#pragma unroll
    for (int mt = 0; mt < 4; mt++)
#pragma unroll
        for (int half = 0; half < 2; half++) {
            float s = 0.f, q = 0.f;
#pragma unroll
            for (int nt = 0; nt < 4; nt++)
#pragma unroll
                for (int j = 0; j < 2; j++) {
                    float v = acc[mt][nt][half * 2 + j];
                    s += v; q += v * v;
                }
            s += __shfl_xor_sync(0xffffffffu, s, 1);
            q += __shfl_xor_sync(0xffffffffu, q, 1);
            s += __shfl_xor_sync(0xffffffffu, s, 2);
            q += __shfl_xor_sync(0xffffffffu, q, 2);
            if (tig == 0) {
                int row = mw + mt * 16 + half * 8 + g;
                sSum[row * 8 + nw] = s;
                sSq[row * 8 + nw]  = q;
            }
        }
    __syncthreads();

    if (tid < 128) {
        float s = 0.f, q = 0.f;
#pragma unroll
        for (int i = 0; i < 8; i++) { s += sSum[tid * 8 + i]; q += sSq[tid * 8 + i]; }
        float mu = s * (1.0f / OD);
        float var = fmaxf(q * (1.0f / OD) - mu * mu, 0.0f);
        sMu[tid] = mu;
        sRs[tid] = rsqrtf(var + LN_EPS);
    }
    __syncthreads();

    // ---- normalize + affine + ReLU + store ----
#pragma unroll
    for (int mt = 0; mt < 4; mt++)
#pragma unroll
        for (int half = 0; half < 2; half++) {
            int row = mw + mt * 16 + half * 8 + g;
            float mu = sMu[row];
            float rs = sRs[row];
            float* orow = out + (size_t)(rowBase + row) * OD;
#pragma unroll
            for (int nt = 0; nt < 4; nt++) {
                int col = nw * 32 + nt * 8 + tig * 2;
                float2 gb0 = *(const float2*)&gamma[col];
                float2 bb0 = *(const float2*)&beta[col];
                float v0 = acc[mt][nt][half * 2 + 0];
                float v1 = acc[mt][nt][half * 2 + 1];
                float2 r2;
                r2.x = fmaxf((v0 - mu) * rs * gb0.x + bb0.x, 0.0f);
                r2.y = fmaxf((v1 - mu) * rs * gb0.y + bb0.y, 0.0f);
                *(float2*)&orow[col] = r2;
            }
        }
}

// ---------------------------------------------------------------------------
extern "C" void kernel_launch(void* const* d_in, const int* in_sizes, int n_in,
                              void* d_out, int out_size)
{
    const float* pos_x   = (const float*)d_in[0];
    const float* xfeat   = (const float*)d_in[1];
    const int*   batch_x = (const int*)  d_in[2];
    const float* pos_y   = (const float*)d_in[3];
    const float* yfeat   = (const float*)d_in[4];
    const int*   batch_y = (const int*)  d_in[5];
    const float* W       = (const float*)d_in[6];
    const float* gamma   = (const float*)d_in[7];
    const float* beta    = (const float*)d_in[8];
    float* out = (float*)d_out;

    prep_kernel<<<KNN_BLOCKS + W_BLOCKS, 256>>>(pos_x, xfeat, batch_x,
                                                pos_y, yfeat, batch_y, W);

    cudaFuncSetAttribute(gemm_mma_kernel,
                         cudaFuncAttributeMaxDynamicSharedMemorySize, G_TOTAL);
    gemm_mma_kernel<<<NY / 128, 512, G_TOTAL>>>(gamma, beta, out);
}

// round 9
// speedup vs baseline: 1.2404x; 1.0098x over previous
#include <cuda_runtime.h>
#include <cuda_bf16.h>
#include <cstdint>
#include <math.h>

// Problem shapes (fixed)
#define NX 4096
#define NY 16384
#define CX 128
#define CY 128
#define OD 256
#define KIN 256
#define BIGD 1e30f
#define W_EPS 1e-16f
#define LN_EPS 1e-5f

// Global scratch: W split only (A never round-trips through global anymore)
__device__ __nv_bfloat16 g_Wh[OD * KIN];
__device__ __nv_bfloat16 g_Wl[OD * KIN];

// ---------------------------------------------------------------------------
// Helpers (baseline PTX, valid for compute_100)
// ---------------------------------------------------------------------------
static __device__ __forceinline__ uint32_t smem_u32(const void* p) {
    uint32_t a;
    asm("{ .reg .u64 t; cvta.to.shared.u64 t, %1; cvt.u32.u64 %0, t; }"
        : "=r"(a) : "l"(p));
    return a;
}

static __device__ __forceinline__ void ldsm_x4(uint32_t addr, uint32_t* r) {
    asm volatile("ldmatrix.sync.aligned.m8n8.x4.shared.b16 {%0,%1,%2,%3}, [%4];"
                 : "=r"(r[0]), "=r"(r[1]), "=r"(r[2]), "=r"(r[3]) : "r"(addr));
}

static __device__ __forceinline__ void mma_bf16(float* d, const uint32_t* a,
                                                uint32_t b0, uint32_t b1) {
    asm volatile(
        "mma.sync.aligned.m16n8k16.row.col.f32.bf16.bf16.f32 "
        "{%0,%1,%2,%3},{%4,%5,%6,%7},{%8,%9},{%0,%1,%2,%3};"
        : "+f"(d[0]), "+f"(d[1]), "+f"(d[2]), "+f"(d[3])
        : "r"(a[0]), "r"(a[1]), "r"(a[2]), "r"(a[3]), "r"(b0), "r"(b1));
}

static __device__ __forceinline__ void cp_async16(uint32_t dst, const void* src) {
    asm volatile("cp.async.cg.shared.global [%0], [%1], 16;" :: "r"(dst), "l"(src));
}
static __device__ __forceinline__ void cp_commit() {
    asm volatile("cp.async.commit_group;" ::: "memory");
}
template <int N>
static __device__ __forceinline__ void cp_wait() {
    asm volatile("cp.async.wait_group %0;" :: "n"(N) : "memory");
}

// Fast hi/lo bf16 split of a float pair
static __device__ __forceinline__ void split_pair(float v0, float v1,
                                                  uint32_t& hp, uint32_t& lp) {
    uint32_t u0 = __float_as_uint(v0), u1 = __float_as_uint(v1);
    asm("prmt.b32 %0, %1, %2, 0x7632;" : "=r"(hp) : "r"(u0), "r"(u1));
    float h0 = __uint_as_float(u0 & 0xFFFF0000u);
    float h1 = __uint_as_float(u1 & 0xFFFF0000u);
    float l0 = v0 - h0, l1 = v1 - h1;
    asm("cvt.rn.bf16x2.f32 %0, %1, %2;" : "=r"(lp) : "f"(l1), "f"(l0));
}

// Branchless top-3 insert (distance only)
#define BINSERT(dd, jj)                                                         \
    do {                                                                        \
        float _d = (dd); int _j = (jj);                                         \
        bool lt0 = _d < d0;                                                     \
        bool lt1 = _d < d1;                                                     \
        bool lt2 = _d < d2v;                                                    \
        d2v = lt1 ? d1 : (lt2 ? _d : d2v); i2 = lt1 ? i1 : (lt2 ? _j : i2);     \
        d1  = lt0 ? d0 : (lt1 ? _d : d1);  i1 = lt0 ? i0 : (lt1 ? _j : i1);     \
        d0  = lt0 ? _d : d0;               i0 = lt0 ? _j : i0;                  \
    } while (0)

// ---------------------------------------------------------------------------
// Kernel 0: W split (packed u32 stores)
// ---------------------------------------------------------------------------
__global__ __launch_bounds__(256)
void wsplit_kernel(const float* __restrict__ W) {
    int base = blockIdx.x * (256 * 4) + threadIdx.x;
    uint32_t* wh = (uint32_t*)g_Wh;
    uint32_t* wl = (uint32_t*)g_Wl;
#pragma unroll
    for (int i = 0; i < 4; i++) {
        int p = base + i * 256;
        float2 v = *(const float2*)&W[p * 2];
        split_pair(v.x, v.y, wh[p], wl[p]);
    }
}

// ---------------------------------------------------------------------------
// Kernel 1 (FUSED): KNN+interp -> smem A tile -> bf16 hi/lo mma GEMM -> LN+ReLU
// Per CTA: 128 query rows x 256 out cols. 512 threads = 16 warps (2m x 8n),
// warp tile 64m x 32n. K = 256 in 8 phases of 32 (B ping-pong, cp.async).
//
// SMEM map (dynamic, 217088 B):
//   A_hi [128 rows][528 B]   @ 0        (67584)  k-major bf16, full K
//   A_lo                     @ 67584    (67584)
//   POS/B region             @ 135168   (81920)
//     B buf0 {BH@+0, BL@+20480}  40960       (stride 80 B per N-row, 32 K)
//     B buf1 @ +40960            40960
//     pos cache: upper half (n<=2560) for B0-prefetch overlap, else full
//   LN stats overlay B region after mainloop
// ---------------------------------------------------------------------------
#define SROW 528
#define A_HI 0
#define A_LO 67584
#define POSB 135168
#define BSTR 80
#define BBUF 40960
#define BLOF 20480
#define G_TOTAL 217088

__global__ __launch_bounds__(512, 1)
void fused_kernel(const float* __restrict__ pos_x,
                  const float* __restrict__ xfeat,
                  const int*   __restrict__ batch_x,
                  const float* __restrict__ pos_y,
                  const float* __restrict__ yfeat,
                  const int*   __restrict__ batch_y,
                  const float* __restrict__ gamma,
                  const float* __restrict__ beta,
                  float* __restrict__ out)
{
    extern __shared__ char smem[];
    const uint32_t sb = smem_u32(smem);
    __shared__ int sbounds[9];

    const int tid  = threadIdx.x;
    const int wid  = tid >> 5;
    const int lane = tid & 31;
    const int rowBase = blockIdx.x * 128;

    // ---- batch boundaries ----
    if (tid < 9) {
        int t = tid;
        int lo = 0, hi = NX;
        while (lo < hi) { int m = (lo + hi) >> 1; if (batch_x[m] < t) lo = m + 1; else hi = m; }
        sbounds[t] = lo;
    }
    __syncthreads();

    const int bmin = batch_y[rowBase];
    const int bmax = batch_y[rowBase + 127];
    const int s0   = sbounds[bmin];
    const int e1   = sbounds[bmax + 1];
    const int n    = e1 - s0;
    const bool early  = (n <= 2560);   // pos in upper half -> B0 prefetch overlaps KNN
    const bool inSmem = (n <= 5120);
    const uint32_t posOff = POSB + (early ? BBUF : 0);

    // ---- B phase loader ----
    auto load_B = [&](int p, uint32_t bb) {
        const int kof = p * 32;
#pragma unroll
        for (int i = 0; i < 2; i++) {
            int idx = tid + i * 512;           // 0..1023
            int r = idx >> 2, kc = idx & 3;
            const size_t gs = (size_t)r * KIN + kof + kc * 8;
            uint32_t off = (uint32_t)(r * BSTR + kc * 16);
            cp_async16(bb + off, &g_Wh[gs]);
            cp_async16(bb + BLOF + off, &g_Wl[gs]);
        }
        cp_commit();
    };

    if (early) load_B(0, sb + POSB);           // prefetch B0 during KNN

    // ---- stage pos segment (x,y,z,|p|^2 as float4) ----
    if (inSmem) {
        for (int i = tid; i < n; i += 512) {
            int j = s0 + i;
            float x = pos_x[j * 3 + 0];
            float y = pos_x[j * 3 + 1];
            float z = pos_x[j * 3 + 2];
            *(float4*)(smem + posOff + (uint32_t)i * 16) =
                make_float4(x, y, z, x * x + y * y + z * z);
        }
    }
    __syncthreads();

    // ---- KNN + interp: each warp handles 8 query rows ----
#pragma unroll 1
    for (int q = 0; q < 8; q++) {
        const int yloc = wid * 8 + q;
        const int yi   = rowBase + yloc;

        const float py0 = pos_y[yi * 3 + 0];
        const float py1 = pos_y[yi * 3 + 1];
        const float py2 = pos_y[yi * 3 + 2];
        const float ny2 = py0 * py0 + py1 * py1 + py2 * py2;
        const int b = batch_y[yi];
        const int s = sbounds[b];
        const int e = sbounds[b + 1];

        float d0 = BIGD, d1 = BIGD, d2v = BIGD;
        int   i0 = 0,    i1 = 0,    i2 = 0;

        if (inSmem) {
            const int ls = s - s0, le = e - s0;
            for (int jl = ls + lane; jl < le; jl += 32) {
                float4 p = *(const float4*)(smem + posOff + (uint32_t)jl * 16);
                float dot = py0 * p.x + py1 * p.y + py2 * p.z;
                float d = fmaxf(ny2 + p.w - 2.0f * dot, 0.0f);
                BINSERT(d, s0 + jl);
            }
        } else {
            for (int j = s + lane; j < e; j += 32) {
                float px0 = pos_x[j * 3 + 0];
                float px1 = pos_x[j * 3 + 1];
                float px2 = pos_x[j * 3 + 2];
                float nx2 = px0 * px0 + px1 * px1 + px2 * px2;
                float dot = py0 * px0 + py1 * px1 + py2 * px2;
                float d = fmaxf(ny2 + nx2 - 2.0f * dot, 0.0f);
                BINSERT(d, j);
            }
        }

        for (int off = 16; off; off >>= 1) {
            float od0 = __shfl_xor_sync(0xffffffffu, d0,  off);
            float od1 = __shfl_xor_sync(0xffffffffu, d1,  off);
            float od2 = __shfl_xor_sync(0xffffffffu, d2v, off);
            int   oi0 = __shfl_xor_sync(0xffffffffu, i0,  off);
            int   oi1 = __shfl_xor_sync(0xffffffffu, i1,  off);
            int   oi2 = __shfl_xor_sync(0xffffffffu, i2,  off);
            BINSERT(od0, oi0);
            BINSERT(od1, oi1);
            BINSERT(od2, oi2);
        }

        const float w0 = 1.0f / fmaxf(d0,  W_EPS);
        const float w1 = 1.0f / fmaxf(d1,  W_EPS);
        const float w2 = 1.0f / fmaxf(d2v, W_EPS);
        const float inv_wsum = 1.0f / (w0 + w1 + w2);

        const float* f0 = xfeat + (size_t)i0 * CX;
        const float* f1 = xfeat + (size_t)i1 * CX;
        const float* f2 = xfeat + (size_t)i2 * CX;
        const float* fy = yfeat + (size_t)yi * CY;

        const int c = lane * 4;
        float4 a0 = *(const float4*)&f0[c];
        float4 a1 = *(const float4*)&f1[c];
        float4 a2 = *(const float4*)&f2[c];
        float4 ay = *(const float4*)&fy[c];
        float v0 = (w0 * a0.x + w1 * a1.x + w2 * a2.x) * inv_wsum;
        float v1 = (w0 * a0.y + w1 * a1.y + w2 * a2.y) * inv_wsum;
        float v2 = (w0 * a0.z + w1 * a1.z + w2 * a2.z) * inv_wsum;
        float v3 = (w0 * a0.w + w1 * a1.w + w2 * a2.w) * inv_wsum;

        const uint32_t arow = (uint32_t)(yloc * SROW + lane * 8);
        uint2 hp, lp;
        split_pair(v0, v1, hp.x, lp.x);
        split_pair(v2, v3, hp.y, lp.y);
        *(uint2*)(smem + A_HI + arow) = hp;
        *(uint2*)(smem + A_LO + arow) = lp;
        split_pair(ay.x, ay.y, hp.x, lp.x);
        split_pair(ay.z, ay.w, hp.y, lp.y);
        *(uint2*)(smem + A_HI + arow + 256) = hp;   // y-half: k = 128 + lane*4
        *(uint2*)(smem + A_LO + arow + 256) = lp;
    }
    __syncthreads();                               // A complete; pos no longer needed

    if (!early) load_B(0, sb + POSB);

    // ---- GEMM mainloop: 8 phases of K=32 ----
    const int g   = lane >> 2;
    const int tig = lane & 3;
    const int mw  = (wid >> 3) * 64;               // warp row base (0/64)
    const int nw  = wid & 7;                       // warp col base = nw*32

    const int quad  = lane >> 3;
    const int lrow  = lane & 7;
    const int aRow  = (quad & 1) * 8 + lrow;
    const int aKoff = (quad >> 1) * 8;
    const int bRow  = ((lane >> 4) * 8) + lrow;
    const int bKoff = ((lane >> 3) & 1) * 8;
    const uint32_t offB = (uint32_t)((nw * 32 + bRow) * BSTR + bKoff * 2);
    const uint32_t aCol = (uint32_t)((mw + aRow) * SROW + aKoff * 2);

    float acc[4][4][4];
#pragma unroll
    for (int mt = 0; mt < 4; mt++)
#pragma unroll
        for (int nt = 0; nt < 4; nt++)
#pragma unroll
            for (int j = 0; j < 4; j++) acc[mt][nt][j] = 0.f;

#pragma unroll 1
    for (int p = 0; p < 8; p++) {
        if (p < 7) {
            load_B(p + 1, sb + POSB + (uint32_t)((p + 1) & 1) * BBUF);
            cp_wait<1>();
        } else {
            cp_wait<0>();
        }
        __syncthreads();

        const uint32_t bB = sb + POSB + (uint32_t)(p & 1) * BBUF + offB;
        const uint32_t aB = sb + A_HI + aCol + (uint32_t)(p * 64);

#pragma unroll
        for (int ks = 0; ks < 2; ks++) {
            const uint32_t kb = (uint32_t)(ks * 32);
            uint32_t Bh[8], Bl[8];
            ldsm_x4(bB + kb, Bh);
            ldsm_x4(bB + 1280 + kb, Bh + 4);       // +16 rows * 80 B
            ldsm_x4(bB + BLOF + kb, Bl);
            ldsm_x4(bB + BLOF + 1280 + kb, Bl + 4);
#pragma unroll
            for (int mt = 0; mt < 4; mt++) {
                uint32_t Ah[4], Al[4];
                const uint32_t aa = aB + (uint32_t)(mt * 16 * SROW) + kb;
                ldsm_x4(aa, Ah);
                ldsm_x4(aa + A_LO, Al);
                // term-major order: RAW distance 4 between touches of same acc
#pragma unroll
                for (int nt = 0; nt < 4; nt++)
                    mma_bf16(acc[mt][nt], Ah, Bh[2 * nt], Bh[2 * nt + 1]);
#pragma unroll
                for (int nt = 0; nt < 4; nt++)
                    mma_bf16(acc[mt][nt], Al, Bh[2 * nt], Bh[2 * nt + 1]);
#pragma unroll
                for (int nt = 0; nt < 4; nt++)
                    mma_bf16(acc[mt][nt], Ah, Bl[2 * nt], Bl[2 * nt + 1]);
            }
        }
        __syncthreads();
    }

    // ---- LayerNorm stats (overlay B region) ----
    float* sSum = (float*)(smem + POSB);           // [128][8]
    float* sSq  = sSum + 1024;
    float* sMu  = sSq + 1024;
    float* sRs  = sMu + 128;

#pragma unroll
    for (int mt = 0; mt < 4; mt++)
#pragma unroll
        for (int half = 0; half < 2; half++) {
            float s = 0.f, q = 0.f;
#pragma unroll
            for (int nt = 0; nt < 4; nt++)
#pragma unroll
                for (int j = 0; j < 2; j++) {
                    float v = acc[mt][nt][half * 2 + j];
                    s += v; q += v * v;
                }
            s += __shfl_xor_sync(0xffffffffu, s, 1);
            q += __shfl_xor_sync(0xffffffffu, q, 1);
            s += __shfl_xor_sync(0xffffffffu, s, 2);
            q += __shfl_xor_sync(0xffffffffu, q, 2);
            if (tig == 0) {
                int row = mw + mt * 16 + half * 8 + g;
                sSum[row * 8 + nw] = s;
                sSq[row * 8 + nw]  = q;
            }
        }
    __syncthreads();

    if (tid < 128) {
        float s = 0.f, q = 0.f;
#pragma unroll
        for (int i = 0; i < 8; i++) { s += sSum[tid * 8 + i]; q += sSq[tid * 8 + i]; }
        float mu = s * (1.0f / OD);
        float var = fmaxf(q * (1.0f / OD) - mu * mu, 0.0f);
        sMu[tid] = mu;
        sRs[tid] = rsqrtf(var + LN_EPS);
    }
    __syncthreads();

    // ---- normalize + affine + ReLU + store ----
#pragma unroll
    for (int mt = 0; mt < 4; mt++)
#pragma unroll
        for (int half = 0; half < 2; half++) {
            int row = mw + mt * 16 + half * 8 + g;
            float mu = sMu[row];
            float rs = sRs[row];
            float* orow = out + (size_t)(rowBase + row) * OD;
#pragma unroll
            for (int nt = 0; nt < 4; nt++) {
                int col = nw * 32 + nt * 8 + tig * 2;
                float2 gb0 = *(const float2*)&gamma[col];
                float2 bb0 = *(const float2*)&beta[col];
                float v0 = acc[mt][nt][half * 2 + 0];
                float v1 = acc[mt][nt][half * 2 + 1];
                float2 r2;
                r2.x = fmaxf((v0 - mu) * rs * gb0.x + bb0.x, 0.0f);
                r2.y = fmaxf((v1 - mu) * rs * gb0.y + bb0.y, 0.0f);
                *(float2*)&orow[col] = r2;
            }
        }
}

// ---------------------------------------------------------------------------
extern "C" void kernel_launch(void* const* d_in, const int* in_sizes, int n_in,
                              void* d_out, int out_size)
{
    const float* pos_x   = (const float*)d_in[0];
    const float* xfeat   = (const float*)d_in[1];
    const int*   batch_x = (const int*)  d_in[2];
    const float* pos_y   = (const float*)d_in[3];
    const float* yfeat   = (const float*)d_in[4];
    const int*   batch_y = (const int*)  d_in[5];
    const float* W       = (const float*)d_in[6];
    const float* gamma   = (const float*)d_in[7];
    const float* beta    = (const float*)d_in[8];
    float* out = (float*)d_out;

    wsplit_kernel<<<32, 256>>>(W);

    cudaFuncSetAttribute(fused_kernel,
                         cudaFuncAttributeMaxDynamicSharedMemorySize, G_TOTAL);
    fused_kernel<<<NY / 128, 512, G_TOTAL>>>(pos_x, xfeat, batch_x, pos_y,
                                             yfeat, batch_y, gamma, beta, out);
}